// round 14
// baseline (speedup 1.0000x reference)
#include <cuda_runtime.h>
#include <math.h>

// FullPairwise neighbor list: M=8 molecules, N=1024 atoms, cutoff 5.2.
// Output (float32 buffer): [2, P] flat atom indices written as floats
// (row 0: i's, row 1: j's), pairs ordered lexicographically by
// (molecule, i, j); trailing elements (incl. the zeros(3) output) zeroed.
//
// SINGLE persistent kernel, 256 all-resident blocks (2 x 512thr per SM —
// measured-best geometry: co-resident blocks hide each other's sync bubbles)
// + software grid barrier. Warp = 2 rows (register-blocked LDS.128 reuse).
// Cutoff: sqrtf correctly rounded & monotone =>
//   sqrtf(d2) <= 5.2f  <=>  d2 <= 27.039999008178710938f (NaN -> false).

#define NMOL 8
#define NATM 1024
#define NROWS 8192
#define NBLK 256
#define NTHR 512
#define C2_EXACT 27.039999008178710938f   // largest f32 with sqrtf(x) <= 5.2f

__device__ int g_blkSum[NBLK];
__device__ unsigned g_arrive;    // monotonic across launches (zero-init once)
__device__ unsigned g_epoch;     // incremented by last arrival of each launch

__device__ __forceinline__ unsigned valid_mask(int iloc, int c) {
    const int ls = iloc + 1 - c * 32;     // first j > i within chunk c
    if (ls <= 0) return 0xFFFFFFFFu;
    return (ls >= 32) ? 0u : (0xFFFFFFFFu << ls);
}

__device__ __forceinline__ int warp_excl_scan(int v, int c) {
    int s = v;
#pragma unroll
    for (int off = 1; off < 32; off <<= 1) {
        int t = __shfl_up_sync(0xFFFFFFFFu, s, off);
        if (c >= off) s += t;
    }
    return s - v;
}

__global__ void __launch_bounds__(NTHR, 2)
fused_kernel(const int* __restrict__ species,
             const float* __restrict__ coords,
             float* __restrict__ out, int out_size) {
    __shared__ float4 s4[1056];       // +1-per-32 padded: idx = a + (a>>5)
    __shared__ int s_rowCnt[32];
    __shared__ int s_rowOff[32];

    const unsigned FULL = 0xFFFFFFFFu;
    const int b = blockIdx.x;
    const int tid = threadIdx.x;
    const int w = tid >> 5;           // warp 0..15, handles rows 2w, 2w+1
    const int c = tid & 31;           // lane = chunk

    const int grow0 = b * 32 + 2 * w; // global flat rows (== output i values)
    const int mb = grow0 & ~(NATM - 1);
    const int iloc0 = grow0 & (NATM - 1);
    const int iloc1 = iloc0 + 1;

    // ---- stage molecule coords (NaN-fill padded atoms) ----
    for (int a = tid; a < NATM; a += NTHR) {
        const int ga = mb + a;
        const float* cp = coords + (size_t)ga * 3;
        float x = cp[0], y = cp[1], z = cp[2];
        if (species[ga] == -1) {
            const float nanv = __int_as_float(0x7fc00000);
            x = nanv; y = nanv; z = nanv;
        }
        s4[a + (a >> 5)] = make_float4(x, y, z, 0.0f);
    }
    __syncthreads();

    // ---- my two row coordinates ----
    const float4 ci0 = s4[iloc0 + (iloc0 >> 5)];
    const float4 ci1 = s4[iloc1 + (iloc1 >> 5)];
    const unsigned valid0 = valid_mask(iloc0, c);
    const unsigned valid1 = valid_mask(iloc1, c);

    // ---- phase A: 32 LDS.128, 64 pair tests -> two register bitmasks ----
    unsigned mask0 = 0u, mask1 = 0u;
    const int sbase = c * 33;         // padded chunk base (conflict-free)
#pragma unroll 4
    for (int l = 0; l < 32; l++) {
        const float4 cj = s4[sbase + l];
        {
            float dx = ci0.x - cj.x, dy = ci0.y - cj.y, dz = ci0.z - cj.z;
            float d2 = fmaf(dz, dz, fmaf(dy, dy, dx * dx));
            mask0 |= ((unsigned)(d2 <= C2_EXACT)) << l;   // NaN -> false
        }
        {
            float dx = ci1.x - cj.x, dy = ci1.y - cj.y, dz = ci1.z - cj.z;
            float d2 = fmaf(dz, dz, fmaf(dy, dy, dx * dx));
            mask1 |= ((unsigned)(d2 <= C2_EXACT)) << l;
        }
    }
    mask0 &= valid0;
    mask1 &= valid1;

    // ---- per-row counts + block-local exclusive row offsets ----
    const int pc0 = __popc(mask0);
    const int pc1 = __popc(mask1);
    const int rs0 = __reduce_add_sync(FULL, pc0);
    const int rs1 = __reduce_add_sync(FULL, pc1);
    if (c == 0) { s_rowCnt[2 * w] = rs0; s_rowCnt[2 * w + 1] = rs1; }
    __syncthreads();
    if (w == 0) {
        const int v = s_rowCnt[c];
        const int e = warp_excl_scan(v, c);
        s_rowOff[c] = e;
        if (c == 31) {
            g_blkSum[b] = e + v;      // block total
            __threadfence();          // visible before barrier arrive
        }
    }
    __syncthreads();

    // ---- hoist emit prefix work (independent of barrier results) ----
    const int pre_o0 = s_rowOff[2 * w] + warp_excl_scan(pc0, c);
    const int pre_o1 = s_rowOff[2 * w + 1] + warp_excl_scan(pc1, c);

    // ---- grid barrier (monotonic epoch: safe across graph replays) ----
    if (tid == 0) {
        unsigned my = atomicAdd(&g_arrive, 1);
        unsigned target = my + 1;
        if ((target & (NBLK - 1)) == 0u)   // last arrival of this launch
            atomicAdd(&g_epoch, 1);
        while ((int)(NBLK * (*(volatile unsigned*)&g_epoch) - target) < 0)
            __nanosleep(32);
        __threadfence();
    }
    __syncthreads();

    // ---- phase B: every warp redundantly reduces the 256 block sums ----
    int bsum = 0, tsum = 0;
#pragma unroll
    for (int q = 0; q < NBLK / 32; q++) {
        const int k = q * 32 + c;
        const int v = __ldcg(&g_blkSum[k]);
        tsum += v;
        if (k < b) bsum += v;
    }
    const int blockBase = __reduce_add_sync(FULL, bsum);
    const int total = __reduce_add_sync(FULL, tsum);

    // ---- phase C: emit pairs (two rows per warp) ----
    const int jb = mb + c * 32;
    if (mask0) {
        int o = blockBase + pre_o0;
        const float rowf = (float)grow0;
        unsigned mm = mask0;
        while (mm) {
            const int l = __ffs(mm) - 1;
            mm &= mm - 1;
            out[o] = rowf;
            out[total + o] = (float)(jb + l);
            o++;
        }
    }
    if (mask1) {
        int o = blockBase + pre_o1;
        const float rowf = (float)(grow0 + 1);
        unsigned mm = mask1;
        while (mm) {
            const int l = __ffs(mm) - 1;
            mm &= mm - 1;
            out[o] = rowf;
            out[total + o] = (float)(jb + l);
            o++;
        }
    }

    // ---- tail: zero past the 2*P payload (covers the zeros(3) output) ----
    const int gtid = b * NTHR + tid;
    for (int idx = gtid; idx < out_size; idx += NBLK * NTHR)
        if (idx >= 2 * total) out[idx] = 0.0f;
}

extern "C" void kernel_launch(void* const* d_in, const int* in_sizes, int n_in,
                              void* d_out, int out_size) {
    const int* species = (const int*)d_in[0];
    const float* coords = (const float*)d_in[1];
    float* out = (float*)d_out;

    fused_kernel<<<NBLK, NTHR>>>(species, coords, out, out_size);
}

// round 16
// speedup vs baseline: 1.2611x; 1.2611x over previous
#include <cuda_runtime.h>
#include <math.h>

// FullPairwise neighbor list: M=8 molecules, N=1024 atoms, cutoff 5.2.
// Output (float32 buffer): [2, P] flat atom indices written as floats
// (row 0: i's, row 1: j's), pairs ordered lexicographically by
// (molecule, i, j); trailing elements (incl. the zeros(3) output) zeroed.
//
// SINGLE persistent kernel, 256 all-resident blocks + software grid barrier.
// 2-row register blocking: 512 threads = 16 warps x 2 rows; each LDS.128 of a
// j-atom serves two pair tests -> smem wavefront traffic halved vs 1 row/warp.
// Cutoff: sqrtf is correctly rounded & monotone, so sqrtf(d2) <= 5.2f
//   <=>  d2 <= 27.039999008178710938f (0x41D851EB) exactly (NaN -> false).

#define NMOL 8
#define NATM 1024
#define NROWS 8192
#define NBLK 256
#define NTHR 512
#define C2_EXACT 27.039999008178710938f   // largest f32 with sqrtf(x) <= 5.2f

__device__ int g_blkSum[NBLK];
__device__ unsigned g_arrive;    // monotonic across launches (zero-init once)
__device__ unsigned g_epoch;     // incremented by last arrival of each launch

__device__ __forceinline__ unsigned valid_mask(int iloc, int c) {
    const int ls = iloc + 1 - c * 32;     // first j > i within chunk c
    if (ls <= 0) return 0xFFFFFFFFu;
    return (ls >= 32) ? 0u : (0xFFFFFFFFu << ls);
}

__global__ void __launch_bounds__(NTHR, 2)
fused_kernel(const int* __restrict__ species,
             const float* __restrict__ coords,
             float* __restrict__ out, int out_size) {
    __shared__ float4 s4[1056];       // +1-per-32 padded: idx = a + (a>>5)
    __shared__ int s_rowCnt[32];
    __shared__ int s_rowOff[32];
    __shared__ int s_base2[2];        // [0]=blockBase, [1]=grandTotal

    const unsigned FULL = 0xFFFFFFFFu;
    const int b = blockIdx.x;
    const int tid = threadIdx.x;
    const int w = tid >> 5;           // warp 0..15, handles rows 2w, 2w+1
    const int c = tid & 31;           // lane = chunk

    const int grow0 = b * 32 + 2 * w; // global flat rows (== output i values)
    const int mb = grow0 & ~(NATM - 1);
    const int iloc0 = grow0 & (NATM - 1);
    const int iloc1 = iloc0 + 1;

    // ---- stage molecule coords (NaN-fill padded atoms) ----
    for (int a = tid; a < NATM; a += NTHR) {
        const int ga = mb + a;
        const float* cp = coords + (size_t)ga * 3;
        float x = cp[0], y = cp[1], z = cp[2];
        if (species[ga] == -1) {
            const float nanv = __int_as_float(0x7fc00000);
            x = nanv; y = nanv; z = nanv;
        }
        s4[a + (a >> 5)] = make_float4(x, y, z, 0.0f);
    }
    __syncthreads();

    // ---- my two row coordinates ----
    const float4 ci0 = s4[iloc0 + (iloc0 >> 5)];
    const float4 ci1 = s4[iloc1 + (iloc1 >> 5)];
    const unsigned valid0 = valid_mask(iloc0, c);
    const unsigned valid1 = valid_mask(iloc1, c);

    // ---- phase A: 32 LDS.128, 64 pair tests -> two register bitmasks ----
    unsigned mask0 = 0u, mask1 = 0u;
    const int sbase = c * 33;         // padded chunk base (conflict-free)
#pragma unroll 4
    for (int l = 0; l < 32; l++) {
        const float4 cj = s4[sbase + l];
        {
            float dx = ci0.x - cj.x, dy = ci0.y - cj.y, dz = ci0.z - cj.z;
            float d2 = fmaf(dz, dz, fmaf(dy, dy, dx * dx));
            mask0 |= ((unsigned)(d2 <= C2_EXACT)) << l;   // NaN -> false
        }
        {
            float dx = ci1.x - cj.x, dy = ci1.y - cj.y, dz = ci1.z - cj.z;
            float d2 = fmaf(dz, dz, fmaf(dy, dy, dx * dx));
            mask1 |= ((unsigned)(d2 <= C2_EXACT)) << l;
        }
    }
    mask0 &= valid0;
    mask1 &= valid1;

    // ---- per-row counts + block-local exclusive row offsets ----
    const int pc0 = __popc(mask0);
    const int pc1 = __popc(mask1);
    const int rs0 = __reduce_add_sync(FULL, pc0);
    const int rs1 = __reduce_add_sync(FULL, pc1);
    if (c == 0) { s_rowCnt[2 * w] = rs0; s_rowCnt[2 * w + 1] = rs1; }
    __syncthreads();
    if (w == 0) {
        int v = s_rowCnt[c];
        int s = v;
#pragma unroll
        for (int off = 1; off < 32; off <<= 1) {
            int t = __shfl_up_sync(FULL, s, off);
            if (c >= off) s += t;
        }
        s_rowOff[c] = s - v;
        if (c == 31) {
            g_blkSum[b] = s;          // block total
            __threadfence();          // visible before barrier arrive
        }
    }
    __syncthreads();

    // ---- grid barrier (monotonic epoch: safe across graph replays) ----
    if (tid == 0) {
        unsigned my = atomicAdd(&g_arrive, 1);
        unsigned target = my + 1;
        if ((target & (NBLK - 1)) == 0u)   // last arrival of this launch
            atomicAdd(&g_epoch, 1);
        while ((int)(NBLK * (*(volatile unsigned*)&g_epoch) - target) < 0)
            __nanosleep(32);
        __threadfence();
    }
    __syncthreads();

    // ---- phase B: redundant prefix over 256 block totals ----
    if (w == 0) {
        int bsum = 0, tsum = 0;
#pragma unroll
        for (int q = 0; q < NBLK / 32; q++) {
            const int k = q * 32 + c;
            const int v = __ldcg(&g_blkSum[k]);
            tsum += v;
            if (k < b) bsum += v;
        }
        bsum = __reduce_add_sync(FULL, bsum);
        tsum = __reduce_add_sync(FULL, tsum);
        if (c == 0) { s_base2[0] = bsum; s_base2[1] = tsum; }
    }
    __syncthreads();

    // ---- phase C: emit pairs (two rows per warp) ----
    const int blockBase = s_base2[0];
    const int total = s_base2[1];
    const int jb = mb + c * 32;
    {   // row 0
        int s = pc0;
#pragma unroll
        for (int off = 1; off < 32; off <<= 1) {
            int t = __shfl_up_sync(FULL, s, off);
            if (c >= off) s += t;
        }
        int o = blockBase + s_rowOff[2 * w] + (s - pc0);
        if (mask0) {
            const float rowf = (float)grow0;
            unsigned mm = mask0;
            while (mm) {
                const int l = __ffs(mm) - 1;
                mm &= mm - 1;
                out[o] = rowf;
                out[total + o] = (float)(jb + l);
                o++;
            }
        }
    }
    {   // row 1
        int s = pc1;
#pragma unroll
        for (int off = 1; off < 32; off <<= 1) {
            int t = __shfl_up_sync(FULL, s, off);
            if (c >= off) s += t;
        }
        int o = blockBase + s_rowOff[2 * w + 1] + (s - pc1);
        if (mask1) {
            const float rowf = (float)(grow0 + 1);
            unsigned mm = mask1;
            while (mm) {
                const int l = __ffs(mm) - 1;
                mm &= mm - 1;
                out[o] = rowf;
                out[total + o] = (float)(jb + l);
                o++;
            }
        }
    }

    // ---- tail: zero past the 2*P payload (covers the zeros(3) output) ----
    const int gtid = b * NTHR + tid;
    for (int idx = gtid; idx < out_size; idx += NBLK * NTHR)
        if (idx >= 2 * total) out[idx] = 0.0f;
}

extern "C" void kernel_launch(void* const* d_in, const int* in_sizes, int n_in,
                              void* d_out, int out_size) {
    const int* species = (const int*)d_in[0];
    const float* coords = (const float*)d_in[1];
    float* out = (float*)d_out;

    fused_kernel<<<NBLK, NTHR>>>(species, coords, out, out_size);
}

// round 17
// speedup vs baseline: 1.2642x; 1.0025x over previous
#include <cuda_runtime.h>
#include <math.h>

// FullPairwise neighbor list: M=8 molecules, N=1024 atoms, cutoff 5.2.
// Output (float32 buffer): [2, P] flat atom indices written as floats
// (row 0: i's, row 1: j's), pairs ordered lexicographically by
// (molecule, i, j); trailing elements (incl. the zeros(3) output) zeroed.
//
// SINGLE persistent kernel, 256 all-resident blocks + software grid barrier
// (R11 structure). Phase A uses packed f32x2 math: SoA smem, each LDS.64
// fetches two adjacent j-atom coords, fma.rn.f32x2 tests both at once.
// Cutoff: sqrtf correctly rounded & monotone => sqrtf(d2) <= 5.2f
//   <=>  d2 <= 27.039999008178710938f (0x41D851EB) exactly (NaN -> false).

#define NMOL 8
#define NATM 1024
#define NROWS 8192
#define NBLK 256
#define NTHR 512
#define C2_EXACT 27.039999008178710938f   // largest f32 with sqrtf(x) <= 5.2f
#define PADIX(a) ((a) + 2 * ((a) >> 5))   // +2 floats per 32: even, bank-safe

__device__ int g_blkSum[NBLK];
__device__ unsigned g_arrive;    // monotonic across launches (zero-init once)
__device__ unsigned g_epoch;     // incremented by last arrival of each launch

typedef unsigned long long u64;

__device__ __forceinline__ u64 pack2(float a, float b) {
    u64 r; asm("mov.b64 %0, {%1, %2};" : "=l"(r) : "f"(a), "f"(b)); return r;
}
__device__ __forceinline__ u64 fma2(u64 a, u64 b, u64 c) {
    u64 d; asm("fma.rn.f32x2 %0, %1, %2, %3;" : "=l"(d) : "l"(a), "l"(b), "l"(c));
    return d;
}
__device__ __forceinline__ u64 mul2(u64 a, u64 b) {
    u64 d; asm("mul.rn.f32x2 %0, %1, %2;" : "=l"(d) : "l"(a), "l"(b)); return d;
}
__device__ __forceinline__ void unpack2(u64 d, float& lo, float& hi) {
    asm("mov.b64 {%0, %1}, %2;" : "=f"(lo), "=f"(hi) : "l"(d));
}

__device__ __forceinline__ unsigned valid_mask(int iloc, int c) {
    const int ls = iloc + 1 - c * 32;     // first j > i within chunk c
    if (ls <= 0) return 0xFFFFFFFFu;
    return (ls >= 32) ? 0u : (0xFFFFFFFFu << ls);
}

__global__ void __launch_bounds__(NTHR, 2)
fused_kernel(const int* __restrict__ species,
             const float* __restrict__ coords,
             float* __restrict__ out, int out_size) {
    __shared__ __align__(16) float sx[1088];
    __shared__ __align__(16) float sy[1088];
    __shared__ __align__(16) float sz[1088];
    __shared__ int s_rowCnt[32];
    __shared__ int s_rowOff[32];
    __shared__ int s_base2[2];        // [0]=blockBase, [1]=grandTotal

    const unsigned FULL = 0xFFFFFFFFu;
    const int b = blockIdx.x;
    const int tid = threadIdx.x;
    const int w = tid >> 5;           // warp 0..15, handles rows 2w, 2w+1
    const int c = tid & 31;           // lane = chunk

    const int grow0 = b * 32 + 2 * w; // global flat rows (== output i values)
    const int mb = grow0 & ~(NATM - 1);
    const int iloc0 = grow0 & (NATM - 1);
    const int iloc1 = iloc0 + 1;

    // ---- stage molecule coords into SoA smem (NaN-fill padded atoms) ----
    for (int a = tid; a < NATM; a += NTHR) {
        const int ga = mb + a;
        const float* cp = coords + (size_t)ga * 3;
        float x = cp[0], y = cp[1], z = cp[2];
        if (species[ga] == -1) {
            const float nanv = __int_as_float(0x7fc00000);
            x = nanv; y = nanv; z = nanv;
        }
        const int p = PADIX(a);
        sx[p] = x; sy[p] = y; sz[p] = z;
    }
    __syncthreads();

    // ---- my two row coordinates, broadcast-packed once ----
    const int p0 = PADIX(iloc0), p1 = PADIX(iloc1);
    const u64 cx0 = pack2(sx[p0], sx[p0]);
    const u64 cy0 = pack2(sy[p0], sy[p0]);
    const u64 cz0 = pack2(sz[p0], sz[p0]);
    const u64 cx1 = pack2(sx[p1], sx[p1]);
    const u64 cy1 = pack2(sy[p1], sy[p1]);
    const u64 cz1 = pack2(sz[p1], sz[p1]);
    const u64 NEG1 = pack2(-1.0f, -1.0f);
    const unsigned valid0 = valid_mask(iloc0, c);
    const unsigned valid1 = valid_mask(iloc1, c);

    // ---- phase A: 16 steps x (2 j-atoms via LDS.64 + f32x2 math) ----
    unsigned mask0 = 0u, mask1 = 0u;
    const int sbase = 34 * c;         // padded float index of my chunk base
#pragma unroll 4
    for (int l = 0; l < 16; l++) {
        const u64 jx = *(const u64*)&sx[sbase + 2 * l];  // atoms 2l, 2l+1
        const u64 jy = *(const u64*)&sy[sbase + 2 * l];
        const u64 jz = *(const u64*)&sz[sbase + 2 * l];
        {   // row 0: two tests in one packed chain
            const u64 dx = fma2(jx, NEG1, cx0);
            const u64 dy = fma2(jy, NEG1, cy0);
            const u64 dz = fma2(jz, NEG1, cz0);
            const u64 d2 = fma2(dx, dx, fma2(dy, dy, mul2(dz, dz)));
            float lo, hi; unpack2(d2, lo, hi);
            mask0 |= ((unsigned)(lo <= C2_EXACT)) << (2 * l);      // NaN->false
            mask0 |= ((unsigned)(hi <= C2_EXACT)) << (2 * l + 1);
        }
        {   // row 1
            const u64 dx = fma2(jx, NEG1, cx1);
            const u64 dy = fma2(jy, NEG1, cy1);
            const u64 dz = fma2(jz, NEG1, cz1);
            const u64 d2 = fma2(dx, dx, fma2(dy, dy, mul2(dz, dz)));
            float lo, hi; unpack2(d2, lo, hi);
            mask1 |= ((unsigned)(lo <= C2_EXACT)) << (2 * l);
            mask1 |= ((unsigned)(hi <= C2_EXACT)) << (2 * l + 1);
        }
    }
    mask0 &= valid0;
    mask1 &= valid1;

    // ---- per-row counts + block-local exclusive row offsets ----
    const int pc0 = __popc(mask0);
    const int pc1 = __popc(mask1);
    const int rs0 = __reduce_add_sync(FULL, pc0);
    const int rs1 = __reduce_add_sync(FULL, pc1);
    if (c == 0) { s_rowCnt[2 * w] = rs0; s_rowCnt[2 * w + 1] = rs1; }
    __syncthreads();
    if (w == 0) {
        int v = s_rowCnt[c];
        int s = v;
#pragma unroll
        for (int off = 1; off < 32; off <<= 1) {
            int t = __shfl_up_sync(FULL, s, off);
            if (c >= off) s += t;
        }
        s_rowOff[c] = s - v;
        if (c == 31) {
            g_blkSum[b] = s;          // block total
            __threadfence();          // visible before barrier arrive
        }
    }
    __syncthreads();

    // ---- grid barrier (monotonic epoch: safe across graph replays) ----
    if (tid == 0) {
        unsigned my = atomicAdd(&g_arrive, 1);
        unsigned target = my + 1;
        if ((target & (NBLK - 1)) == 0u)   // last arrival of this launch
            atomicAdd(&g_epoch, 1);
        while ((int)(NBLK * (*(volatile unsigned*)&g_epoch) - target) < 0)
            __nanosleep(32);
        __threadfence();
    }
    __syncthreads();

    // ---- phase B: redundant prefix over 256 block totals (warp 0) ----
    if (w == 0) {
        int bsum = 0, tsum = 0;
#pragma unroll
        for (int q = 0; q < NBLK / 32; q++) {
            const int k = q * 32 + c;
            const int v = __ldcg(&g_blkSum[k]);
            tsum += v;
            if (k < b) bsum += v;
        }
        bsum = __reduce_add_sync(FULL, bsum);
        tsum = __reduce_add_sync(FULL, tsum);
        if (c == 0) { s_base2[0] = bsum; s_base2[1] = tsum; }
    }
    __syncthreads();

    // ---- phase C: emit pairs (two rows per warp) ----
    const int blockBase = s_base2[0];
    const int total = s_base2[1];
    const int jb = mb + c * 32;
    {   // row 0
        int s = pc0;
#pragma unroll
        for (int off = 1; off < 32; off <<= 1) {
            int t = __shfl_up_sync(FULL, s, off);
            if (c >= off) s += t;
        }
        int o = blockBase + s_rowOff[2 * w] + (s - pc0);
        if (mask0) {
            const float rowf = (float)grow0;
            unsigned mm = mask0;
            while (mm) {
                const int l = __ffs(mm) - 1;
                mm &= mm - 1;
                out[o] = rowf;
                out[total + o] = (float)(jb + l);
                o++;
            }
        }
    }
    {   // row 1
        int s = pc1;
#pragma unroll
        for (int off = 1; off < 32; off <<= 1) {
            int t = __shfl_up_sync(FULL, s, off);
            if (c >= off) s += t;
        }
        int o = blockBase + s_rowOff[2 * w + 1] + (s - pc1);
        if (mask1) {
            const float rowf = (float)(grow0 + 1);
            unsigned mm = mask1;
            while (mm) {
                const int l = __ffs(mm) - 1;
                mm &= mm - 1;
                out[o] = rowf;
                out[total + o] = (float)(jb + l);
                o++;
            }
        }
    }

    // ---- tail: zero past the 2*P payload (covers the zeros(3) output) ----
    const int gtid = b * NTHR + tid;
    for (int idx = gtid; idx < out_size; idx += NBLK * NTHR)
        if (idx >= 2 * total) out[idx] = 0.0f;
}

extern "C" void kernel_launch(void* const* d_in, const int* in_sizes, int n_in,
                              void* d_out, int out_size) {
    const int* species = (const int*)d_in[0];
    const float* coords = (const float*)d_in[1];
    float* out = (float*)d_out;

    fused_kernel<<<NBLK, NTHR>>>(species, coords, out, out_size);
}